// round 1
// baseline (speedup 1.0000x reference)
#include <cuda_runtime.h>
#include <math.h>

// ---------------- scratch (no allocations allowed) ----------------
__device__ float g_lbar[49 * 100];   // sum over 4096 patches (divide later)
__device__ float g_W[49 * 52];       // fused weights W[p][q] = wop[p]*kT[p,q], rows padded to 52

// ---------------- kernel 0: zero the reduction scratch ----------------
__global__ void k_zero() {
    int t = blockIdx.x * blockDim.x + threadIdx.x;
    if (t < 49 * 100) g_lbar[t] = 0.0f;
}

// ---------------- kernel 1: logits -> lbar sums (HBM-bound) ----------------
// grid = (1600, 4): x = b*100+n plane, y = 28-row chunk. block = 112 threads (one per column w).
__global__ void k_reduce(const float* __restrict__ logits) {
    const int plane = blockIdx.x;                 // b*100 + n
    const int n = plane % 100;
    const float* base = logits + (size_t)plane * 12544 + (size_t)blockIdx.y * 28 * 112;
    const int t = threadIdx.x;                    // 0..111 = column w
    __shared__ float s[49];
    if (t < 49) s[t] = 0.0f;
    __syncthreads();

    float acc[7];
#pragma unroll
    for (int r = 0; r < 7; r++) acc[r] = 0.0f;
    // 28 rows; 28 % 7 == 0 so r = (row within chunk) % 7 is the global h%7
#pragma unroll
    for (int g = 0; g < 4; g++) {
#pragma unroll
        for (int r = 0; r < 7; r++) {
            acc[r] += base[(g * 7 + r) * 112 + t];
        }
    }
    const int c = t % 7;
#pragma unroll
    for (int r = 0; r < 7; r++) atomicAdd(&s[r * 7 + c], acc[r]);
    __syncthreads();
    if (t < 49) atomicAdd(&g_lbar[t * 100 + n], s[t]);
}

// ---------------- kernel 2: per-p params, Gaussian, pad, bilinear translate ----------------
// single block, 256 threads
__global__ void k_params(const float* __restrict__ sigx, const float* __restrict__ sigy,
                         const float* __restrict__ opac, const float* __restrict__ rho) {
    __shared__ float sLb[49 * 100];
    __shared__ float ws[4 * 49];
    __shared__ float kp[49 * 49];   // padded 7x7 kernels, row per p
    const int t = threadIdx.x;

    for (int i = t; i < 4900; i += 256) sLb[i] = g_lbar[i] * (1.0f / 4096.0f);
    __syncthreads();

    if (t < 196) {
        const int p = t >> 2, w = t & 3;
        const float* v = (w == 0) ? sigx : (w == 1) ? sigy : (w == 2) ? opac : rho;
        float s = 0.0f;
        const float* row = &sLb[p * 100];
#pragma unroll 4
        for (int n = 0; n < 100; n++) s += row[n] * v[n];
        ws[w * 49 + p] = s;
    }
    __syncthreads();

    if (t < 49) {
        const int p = t;
        const float wsx = ws[p], wsy = ws[49 + p], wop = ws[98 + p], wrho = ws[147 + p];
        const float a = wsx * wsx + 1e-5f;
        const float dd = wsy * wsy + 1e-5f;
        const float b = wrho * wsx * wsy;
        const float det = a * dd - b * b;
        const float ia = dd / det, ib = -b / det, id = a / det;
        const float norm = 1.0f / (6.283185307179586f * sqrtf(det));

        float* kr = &kp[p * 49];
#pragma unroll
        for (int i = 0; i < 49; i++) kr[i] = 0.0f;

        float m = -1e30f;
        for (int u = 0; u < 5; u++) {
            const float x = -5.0f + 2.5f * (float)u;
            for (int v2 = 0; v2 < 5; v2++) {
                const float y = -5.0f + 2.5f * (float)v2;
                const float z = -0.5f * (ia * x * x + 2.0f * ib * x * y + id * y * y);
                const float kv = expf(z) * norm;
                m = fmaxf(m, kv);
                kr[(u + 1) * 7 + (v2 + 1)] = kv;
            }
        }
        const float invm = 1.0f / m;
        for (int u = 0; u < 5; u++)
            for (int v2 = 0; v2 < 5; v2++) kr[(u + 1) * 7 + (v2 + 1)] *= invm;

        // bilinear translate, exactly like reference
        const int rr = p / 7, cc = p % 7;
        const float tx = 1.0f - 2.0f * (float)cc / 7.0f;
        const float ty = 1.0f - 2.0f * (float)rr / 7.0f;
        const float sxp = tx * 3.0f;   // tx*(COL-1)/2
        const float syp = ty * 3.0f;   // ty*(ROW-1)/2

        for (int i = 0; i < 7; i++) {
            const float ii = (float)i + syp;
            const float i0 = floorf(ii);
            const float wi = ii - i0;
            for (int j = 0; j < 7; j++) {
                const float jj = (float)j + sxp;
                const float j0 = floorf(jj);
                const float wj = jj - j0;
                float v00, v01, v10, v11;
                {
                    auto G = [&](float iz, float jz) -> float {
                        if (iz < 0.0f || iz > 6.0f || jz < 0.0f || jz > 6.0f) return 0.0f;
                        return kr[(int)iz * 7 + (int)jz];
                    };
                    v00 = G(i0, j0);
                    v01 = G(i0, j0 + 1.0f);
                    v10 = G(i0 + 1.0f, j0);
                    v11 = G(i0 + 1.0f, j0 + 1.0f);
                }
                const float kT = v00 * (1.0f - wi) * (1.0f - wj) + v01 * (1.0f - wi) * wj +
                                 v10 * wi * (1.0f - wj) + v11 * wi * wj;
                g_W[p * 52 + i * 7 + j] = wop * kT;
            }
        }
    }
}

// ---------------- kernel 3: apply splat weights (49x49 per patch) ----------------
// grid = 256 (bc * 2 halves), block = 128 (one thread per patch in the half-plane)
__global__ void __launch_bounds__(128) k_apply(const float* __restrict__ inp, float* __restrict__ out) {
    __shared__ float sIn[128 * 53];                 // one 49-row per patch, pad 53 (gcd(53,32)=1)
    __shared__ __align__(16) float sW[49 * 52];     // W rows padded to 52 floats (16B-aligned rows)

    const int blk = blockIdx.x;
    const int bc = blk >> 1;          // b*8 + c
    const int half = blk & 1;
    const int b = bc >> 3, c = bc & 7;
    const float* src = inp + ((size_t)b * 64 + c) * 12544 + (size_t)half * 56 * 112;
    float* dst = out + (size_t)bc * 12544 + (size_t)half * 56 * 112;
    const int t = threadIdx.x;

    for (int i = t; i < 49 * 52; i += 128) sW[i] = g_W[i];

    // coalesced load of 56x112 band, scattered into per-patch rows
#pragma unroll
    for (int k = 0; k < 49; k++) {
        const int o = k * 128 + t;
        const int h = o / 112, w = o % 112;
        const int patch = (h / 7) * 16 + (w / 7);
        const int pos = (h % 7) * 7 + (w % 7);
        sIn[patch * 53 + pos] = src[o];
    }
    __syncthreads();

    float acc[49];
#pragma unroll
    for (int q = 0; q < 49; q++) acc[q] = 0.0f;

    const float* myrow = &sIn[t * 53];
#pragma unroll 7
    for (int p = 0; p < 49; p++) {
        const float xin = myrow[p];
        const float4* w4 = (const float4*)(sW + p * 52);   // warp-broadcast LDS.128
#pragma unroll
        for (int g = 0; g < 12; g++) {
            const float4 wv = w4[g];
            acc[4 * g + 0] = fmaf(xin, wv.x, acc[4 * g + 0]);
            acc[4 * g + 1] = fmaf(xin, wv.y, acc[4 * g + 1]);
            acc[4 * g + 2] = fmaf(xin, wv.z, acc[4 * g + 2]);
            acc[4 * g + 3] = fmaf(xin, wv.w, acc[4 * g + 3]);
        }
        acc[48] = fmaf(xin, sW[p * 52 + 48], acc[48]);
    }

    // in-place writeback into this lane's own row (each lane reads only its own row)
    float* orow = &sIn[t * 53];
#pragma unroll
    for (int q = 0; q < 49; q++) orow[q] = acc[q];
    __syncthreads();

    // coalesced store
#pragma unroll
    for (int k = 0; k < 49; k++) {
        const int o = k * 128 + t;
        const int h = o / 112, w = o % 112;
        const int patch = (h / 7) * 16 + (w / 7);
        const int pos = (h % 7) * 7 + (w % 7);
        dst[o] = sIn[patch * 53 + pos];
    }
}

// ---------------- launcher ----------------
extern "C" void kernel_launch(void* const* d_in, const int* in_sizes, int n_in,
                              void* d_out, int out_size) {
    const float* inp    = (const float*)d_in[0];  // (16,64,112,112)
    const float* logits = (const float*)d_in[1];  // (16,100,112,112)
    const float* sigx   = (const float*)d_in[2];  // (100)
    const float* sigy   = (const float*)d_in[3];  // (100)
    const float* opac   = (const float*)d_in[4];  // (100,1) flat
    const float* rho    = (const float*)d_in[5];  // (100,1) flat
    float* out = (float*)d_out;                   // (16,8,112,112)

    k_zero<<<20, 256>>>();
    k_reduce<<<dim3(1600, 4), 112>>>(logits);
    k_params<<<1, 256>>>(sigx, sigy, opac, rho);
    k_apply<<<256, 128>>>(inp, out);
}

// round 2
// speedup vs baseline: 1.2755x; 1.2755x over previous
#include <cuda_runtime.h>
#include <math.h>

// ---------------- scratch (no allocations allowed) ----------------
__device__ float g_lbar[49 * 100];   // sum over 4096 patches (divide later)
__device__ float g_W[49 * 52];       // fused weights W[p][q] = wop[p]*kT[p,q], rows padded to 52

// ---------------- kernel 0: zero the reduction scratch ----------------
__global__ void k_zero() {
    int t = blockIdx.x * blockDim.x + threadIdx.x;
    if (t < 49 * 100) g_lbar[t] = 0.0f;
}

// ---------------- kernel 1: logits -> lbar sums (HBM-bound) ----------------
// grid = 1600 (one plane b*100+n per block), block = 224 threads.
// Thread t: c4 = t%28 (float4 column), rb = t/28 (14-row band).
// Rows r = rb*14 + k, phase = r%7 = k%7 (14 % 7 == 0).
__global__ void __launch_bounds__(224) k_reduce(const float* __restrict__ logits) {
    const int plane = blockIdx.x;                 // b*100 + n
    const int n = plane % 100;
    const float4* __restrict__ base4 =
        (const float4*)(logits + (size_t)plane * 12544);
    const int t = threadIdx.x;
    const int c4 = t % 28;
    const int rb = t / 28;

    __shared__ float s[224 * 29];   // [t][28] padded to 29 (conflict-free)
    __shared__ float s2[784];       // [c4][28]

    float acc[7][4];
#pragma unroll
    for (int i = 0; i < 7; i++)
#pragma unroll
        for (int j = 0; j < 4; j++) acc[i][j] = 0.0f;

#pragma unroll
    for (int k = 0; k < 14; k++) {
        const int r = rb * 14 + k;
        const float4 v = base4[r * 28 + c4];
        const int ph = k % 7;
        acc[ph][0] += v.x;
        acc[ph][1] += v.y;
        acc[ph][2] += v.z;
        acc[ph][3] += v.w;
    }

#pragma unroll
    for (int ph = 0; ph < 7; ph++)
#pragma unroll
        for (int j = 0; j < 4; j++) s[t * 29 + ph * 4 + j] = acc[ph][j];
    __syncthreads();

    // reduce over the 8 row-bands: s2[c4*28 + i] = sum_rb s[(rb*28+c4)*29 + i]
#pragma unroll
    for (int u = 0; u < 4; u++) {
        const int id = u * 224 + t;
        if (id < 784) {
            const int cc4 = id / 28;
            const int i = id % 28;
            float sum = 0.0f;
#pragma unroll
            for (int r8 = 0; r8 < 8; r8++) sum += s[(r8 * 28 + cc4) * 29 + i];
            s2[cc4 * 28 + i] = sum;
        }
    }
    __syncthreads();

    // fold column groups into the 49 (row-phase, col-phase) bins
    if (t < 49) {
        const int rp = t / 7, cp = t % 7;
        float sum = 0.0f;
#pragma unroll
        for (int cc4 = 0; cc4 < 28; cc4++) {
            const int j = (cp + 112 - 4 * cc4) % 7;  // which of the 4 lanes maps to cp
            if (j < 4) sum += s2[cc4 * 28 + rp * 4 + j];
        }
        atomicAdd(&g_lbar[t * 100 + n], sum);
    }
}

// ---------------- kernel 2: per-p params, Gaussian, pad, bilinear translate ----------------
// single block, 256 threads
__global__ void k_params(const float* __restrict__ sigx, const float* __restrict__ sigy,
                         const float* __restrict__ opac, const float* __restrict__ rho) {
    __shared__ float sLb[49 * 100];
    __shared__ float ws[4 * 49];
    __shared__ float kp[49 * 49];   // padded 7x7 kernels, row per p
    const int t = threadIdx.x;

    for (int i = t; i < 4900; i += 256) sLb[i] = g_lbar[i] * (1.0f / 4096.0f);
    __syncthreads();

    if (t < 196) {
        const int p = t >> 2, w = t & 3;
        const float* v = (w == 0) ? sigx : (w == 1) ? sigy : (w == 2) ? opac : rho;
        float s = 0.0f;
        const float* row = &sLb[p * 100];
#pragma unroll 4
        for (int n = 0; n < 100; n++) s += row[n] * v[n];
        ws[w * 49 + p] = s;
    }
    __syncthreads();

    if (t < 49) {
        const int p = t;
        const float wsx = ws[p], wsy = ws[49 + p], wop = ws[98 + p], wrho = ws[147 + p];
        const float a = wsx * wsx + 1e-5f;
        const float dd = wsy * wsy + 1e-5f;
        const float b = wrho * wsx * wsy;
        const float det = a * dd - b * b;
        const float ia = dd / det, ib = -b / det, id = a / det;
        const float norm = 1.0f / (6.283185307179586f * sqrtf(det));

        float* kr = &kp[p * 49];
#pragma unroll
        for (int i = 0; i < 49; i++) kr[i] = 0.0f;

        float m = -1e30f;
        for (int u = 0; u < 5; u++) {
            const float x = -5.0f + 2.5f * (float)u;
            for (int v2 = 0; v2 < 5; v2++) {
                const float y = -5.0f + 2.5f * (float)v2;
                const float z = -0.5f * (ia * x * x + 2.0f * ib * x * y + id * y * y);
                const float kv = expf(z) * norm;
                m = fmaxf(m, kv);
                kr[(u + 1) * 7 + (v2 + 1)] = kv;
            }
        }
        const float invm = 1.0f / m;
        for (int u = 0; u < 5; u++)
            for (int v2 = 0; v2 < 5; v2++) kr[(u + 1) * 7 + (v2 + 1)] *= invm;

        // bilinear translate, exactly like reference
        const int rr = p / 7, cc = p % 7;
        const float tx = 1.0f - 2.0f * (float)cc / 7.0f;
        const float ty = 1.0f - 2.0f * (float)rr / 7.0f;
        const float sxp = tx * 3.0f;   // tx*(COL-1)/2
        const float syp = ty * 3.0f;   // ty*(ROW-1)/2

        for (int i = 0; i < 7; i++) {
            const float ii = (float)i + syp;
            const float i0 = floorf(ii);
            const float wi = ii - i0;
            for (int j = 0; j < 7; j++) {
                const float jj = (float)j + sxp;
                const float j0 = floorf(jj);
                const float wj = jj - j0;
                float v00, v01, v10, v11;
                {
                    auto G = [&](float iz, float jz) -> float {
                        if (iz < 0.0f || iz > 6.0f || jz < 0.0f || jz > 6.0f) return 0.0f;
                        return kr[(int)iz * 7 + (int)jz];
                    };
                    v00 = G(i0, j0);
                    v01 = G(i0, j0 + 1.0f);
                    v10 = G(i0 + 1.0f, j0);
                    v11 = G(i0 + 1.0f, j0 + 1.0f);
                }
                const float kT = v00 * (1.0f - wi) * (1.0f - wj) + v01 * (1.0f - wi) * wj +
                                 v10 * wi * (1.0f - wj) + v11 * wi * wj;
                g_W[p * 52 + i * 7 + j] = wop * kT;
            }
        }
    }
}

// ---------------- kernel 3: apply splat weights (49x49 per patch) ----------------
// grid = 512 (bc * 4 quarter-bands of 28 rows), block = 256 (64 patches x 4 q-splits)
__global__ void __launch_bounds__(256) k_apply(const float* __restrict__ inp, float* __restrict__ out) {
    __shared__ float sIn[64 * 53];                  // one 49-row per patch, pad 53
    __shared__ __align__(16) float sW[49 * 52];     // W rows padded to 52 floats

    const int blk = blockIdx.x;
    const int bc = blk >> 2;          // b*8 + c
    const int quarter = blk & 3;
    const int b = bc >> 3, c = bc & 7;
    const float* src = inp + ((size_t)b * 64 + c) * 12544 + (size_t)quarter * 28 * 112;
    float* dst = out + (size_t)bc * 12544 + (size_t)quarter * 28 * 112;
    const int t = threadIdx.x;

    for (int i = t; i < 49 * 52; i += 256) sW[i] = g_W[i];

    // coalesced load of 28x112 band, scattered into per-patch rows
#pragma unroll
    for (int k = 0; k < 13; k++) {
        const int o = k * 256 + t;
        if (o < 3136) {
            const int h = o / 112, w = o % 112;
            const int patch = (h / 7) * 16 + (w / 7);
            const int pos = (h % 7) * 7 + (w % 7);
            sIn[patch * 53 + pos] = src[o];
        }
    }
    __syncthreads();

    // compute: warp = 32 consecutive patches with same q-quarter (broadcast W reads)
    const int qq = t >> 6;            // 0..3
    const int patch = t & 63;
    const int q0 = 12 * qq;           // 12,12,12,13 outputs
    const bool last = (qq == 3);

    float acc[13];
#pragma unroll
    for (int u = 0; u < 13; u++) acc[u] = 0.0f;

    const float* myrow = &sIn[patch * 53];
#pragma unroll 7
    for (int p = 0; p < 49; p++) {
        const float xin = myrow[p];
        const float4* w4 = (const float4*)(sW + p * 52 + q0);  // 16B-aligned (q0 % 4 == 0)
#pragma unroll
        for (int g = 0; g < 3; g++) {
            const float4 wv = w4[g];
            acc[4 * g + 0] = fmaf(xin, wv.x, acc[4 * g + 0]);
            acc[4 * g + 1] = fmaf(xin, wv.y, acc[4 * g + 1]);
            acc[4 * g + 2] = fmaf(xin, wv.z, acc[4 * g + 2]);
            acc[4 * g + 3] = fmaf(xin, wv.w, acc[4 * g + 3]);
        }
        if (last) acc[12] = fmaf(xin, sW[p * 52 + 48], acc[12]);
    }
    __syncthreads();   // all reads of sIn done before overwrite

    // writeback into this patch's row (4 threads per patch, disjoint q ranges)
#pragma unroll
    for (int u = 0; u < 12; u++) sIn[patch * 53 + q0 + u] = acc[u];
    if (last) sIn[patch * 53 + 48] = acc[12];
    __syncthreads();

    // coalesced store
#pragma unroll
    for (int k = 0; k < 13; k++) {
        const int o = k * 256 + t;
        if (o < 3136) {
            const int h = o / 112, w = o % 112;
            const int patch2 = (h / 7) * 16 + (w / 7);
            const int pos = (h % 7) * 7 + (w % 7);
            dst[o] = sIn[patch2 * 53 + pos];
        }
    }
}

// ---------------- launcher ----------------
extern "C" void kernel_launch(void* const* d_in, const int* in_sizes, int n_in,
                              void* d_out, int out_size) {
    const float* inp    = (const float*)d_in[0];  // (16,64,112,112)
    const float* logits = (const float*)d_in[1];  // (16,100,112,112)
    const float* sigx   = (const float*)d_in[2];  // (100)
    const float* sigy   = (const float*)d_in[3];  // (100)
    const float* opac   = (const float*)d_in[4];  // (100,1) flat
    const float* rho    = (const float*)d_in[5];  // (100,1) flat
    float* out = (float*)d_out;                   // (16,8,112,112)

    k_zero<<<20, 256>>>();
    k_reduce<<<1600, 224>>>(logits);
    k_params<<<1, 256>>>(sigx, sigy, opac, rho);
    k_apply<<<512, 256>>>(inp, out);
}